// round 1
// baseline (speedup 1.0000x reference)
#include <cuda_runtime.h>
#include <cstdint>

// Problem constants
#define B_   32
#define C_   3
#define H_   128
#define W_   128
#define N_   1024
#define K_   (C_*H_*W_)      // 49152
#define ROWS_ (C_*H_)        // 384 rows of W_=128 elements each
#define KS_  148             // K-split slabs (one CTA-pair wave, 2 CTAs/SM)
#define NT_  2               // N tiles per slab
#define NPC_ (N_/NT_)        // 512 neurons per CTA (2 per thread)
#define XS_STRIDE 36         // padded smem row stride (floats): 144B, 16B aligned, conflict-free

// Device scratch (no allocations allowed)
__device__ float g_gy [H_*N_];      // gy[h][n]
__device__ float g_gxn[W_*N_];      // gx[w][n] * norm[n]
__device__ float g_part[KS_*B_*N_]; // split-K partials

// ---- packed f32x2 helpers (Blackwell; ptxas never emits FFMA2 from C++) ----
__device__ __forceinline__ uint64_t ffma2(uint64_t a, uint64_t b, uint64_t c){
    uint64_t d; asm("fma.rn.f32x2 %0, %1, %2, %3;" : "=l"(d) : "l"(a), "l"(b), "l"(c)); return d;
}
__device__ __forceinline__ uint64_t fmul2(uint64_t a, uint64_t b){
    uint64_t d; asm("mul.rn.f32x2 %0, %1, %2;" : "=l"(d) : "l"(a), "l"(b)); return d;
}
__device__ __forceinline__ void unpk(uint64_t v, float& lo, float& hi){
    asm("mov.b64 {%0, %1}, %2;" : "=f"(lo), "=f"(hi) : "l"(v));
}
__device__ __forceinline__ uint64_t dup2(float v){
    uint64_t d; asm("mov.b64 %0, {%1, %1};" : "=l"(d) : "f"(v)); return d;
}

// ---- Kernel 1: build gy / gx*norm tables. One warp per neuron. ----
__global__ void build_tables(const float* __restrict__ mu_x, const float* __restrict__ mu_y,
                             const float* __restrict__ sig_x, const float* __restrict__ sig_y)
{
    int wid  = blockIdx.x * (blockDim.x >> 5) + (threadIdx.x >> 5);
    int lane = threadIdx.x & 31;
    if (wid >= N_) return;

    float mx  = mu_x[wid], my = mu_y[wid];
    float isx = 1.f / sig_x[wid], isy = 1.f / sig_y[wid];

    float gxv[4], gyv[4];
    float sx2 = 0.f, sy2 = 0.f;
#pragma unroll
    for (int j = 0; j < 4; j++) {
        int i = lane + 32*j;                      // H_ == W_ == 128
        float g  = (float)i * (1.f/127.f);
        float tx = (g - mx) * isx;
        float vx = expf(-0.5f * tx * tx);
        gxv[j] = vx; sx2 += vx * vx;
        float ty = (g - my) * isy;
        float vy = expf(-0.5f * ty * ty);
        gyv[j] = vy; sy2 += vy * vy;
    }
#pragma unroll
    for (int o = 16; o; o >>= 1) {
        sx2 += __shfl_xor_sync(0xffffffffu, sx2, o);
        sy2 += __shfl_xor_sync(0xffffffffu, sy2, o);
    }
    // mask = gy*gx * sqrt(H*W / (Sy*Sx))   (C cancels)
    float nrm = sqrtf((float)(H_*W_) / (sx2 * sy2));
#pragma unroll
    for (int j = 0; j < 4; j++) {
        int i = lane + 32*j;
        g_gxn[i*N_ + wid] = gxv[j] * nrm;
        g_gy [i*N_ + wid] = gyv[j];
    }
}

// ---- Kernel 2: main masked GEMM, split-K, f32x2 FMAs ----
// Thread t owns neurons (n, n+1); accumulates all 32 batches as b-pairs in f32x2.
__global__ __launch_bounds__(256, 2) void main_kernel(const float* __restrict__ x,
                                                      const float* __restrict__ wgt)
{
    __shared__ __align__(16) float xs[W_ * XS_STRIDE];

    const int t    = threadIdx.x;
    const int slab = blockIdx.x;
    const int n    = blockIdx.y * NPC_ + 2*t;
    const int r0   = ( slab      * ROWS_) / KS_;
    const int r1   = ((slab + 1) * ROWS_) / KS_;

    uint64_t acc0[16], acc1[16];
#pragma unroll
    for (int j = 0; j < 16; j++) { acc0[j] = 0ull; acc1[j] = 0ull; }

    const int bld = t >> 3;      // batch this thread stages (0..31)
    const int wl  = t & 7;       // w phase for staging

    for (int r = r0; r < r1; ++r) {
        __syncthreads();                       // protect previous iteration's reads
        {
            const float* xrow = x + bld*K_ + r*W_;
#pragma unroll
            for (int i = 0; i < 16; i++) {
                int w = wl + 8*i;              // stride-8: coalesced LDG, conflict-free STS
                xs[w*XS_STRIDE + bld] = xrow[w];
            }
        }
        __syncthreads();

        const int h = r & (H_ - 1);
        const uint64_t gy2 = *(const uint64_t*)(g_gy + h*N_ + n);   // n even -> 8B aligned
        const float* wrow = wgt + (size_t)r * W_ * N_ + n;
        const float* gxp  = g_gxn + n;

        // one-ahead register prefetch of weights + gx
        uint64_t wv = *(const uint64_t*)(wrow);
        uint64_t gx = *(const uint64_t*)(gxp);
#pragma unroll 4
        for (int w = 0; w < W_; ++w) {
            const int wn = (w + 1) & (W_ - 1);            // wraps: always in-bounds
            uint64_t wv_n = *(const uint64_t*)(wrow + wn*N_);
            uint64_t gx_n = *(const uint64_t*)(gxp  + wn*N_);

            uint64_t wm2 = fmul2(fmul2(wv, gy2), gx);     // masked weights for (n, n+1)
            float m0, m1; unpk(wm2, m0, m1);
            uint64_t wd0 = dup2(m0), wd1 = dup2(m1);

            const ulonglong2* xp = (const ulonglong2*)(xs + w*XS_STRIDE);
#pragma unroll
            for (int q = 0; q < 8; q++) {
                ulonglong2 v = xp[q];                     // LDS.128: b-pairs (4q,4q+1),(4q+2,4q+3)
                acc0[2*q  ] = ffma2(v.x, wd0, acc0[2*q  ]);
                acc0[2*q+1] = ffma2(v.y, wd0, acc0[2*q+1]);
                acc1[2*q  ] = ffma2(v.x, wd1, acc1[2*q  ]);
                acc1[2*q+1] = ffma2(v.y, wd1, acc1[2*q+1]);
            }
            wv = wv_n; gx = gx_n;
        }
    }

    // epilogue: partials[slab][b][n], coalesced float2 stores
    float* pp = g_part + (size_t)slab * (B_*N_) + n;
#pragma unroll
    for (int j = 0; j < 16; j++) {
        float a0, a1, b0, b1;
        unpk(acc0[j], a0, a1);     // b = 2j, 2j+1 for neuron n
        unpk(acc1[j], b0, b1);     // b = 2j, 2j+1 for neuron n+1
        *(float2*)(pp + (2*j    )*N_) = make_float2(a0, b0);
        *(float2*)(pp + (2*j + 1)*N_) = make_float2(a1, b1);
    }
}

// ---- Kernel 3: deterministic split-K reduction ----
__global__ void reduce_kernel(float* __restrict__ out)
{
    int i = blockIdx.x * blockDim.x + threadIdx.x;   // 0 .. B_*N_-1
    float s0 = 0.f, s1 = 0.f, s2 = 0.f, s3 = 0.f;
#pragma unroll 1
    for (int s = 0; s < KS_; s += 4) {               // 148 = 4*37
        s0 += g_part[(size_t)(s    ) * (B_*N_) + i];
        s1 += g_part[(size_t)(s + 1) * (B_*N_) + i];
        s2 += g_part[(size_t)(s + 2) * (B_*N_) + i];
        s3 += g_part[(size_t)(s + 3) * (B_*N_) + i];
    }
    out[i] = (s0 + s1) + (s2 + s3);
}

extern "C" void kernel_launch(void* const* d_in, const int* in_sizes, int n_in,
                              void* d_out, int out_size)
{
    const float* x    = (const float*)d_in[0];
    const float* mux  = (const float*)d_in[1];
    const float* muy  = (const float*)d_in[2];
    const float* sx   = (const float*)d_in[3];
    const float* sy   = (const float*)d_in[4];
    const float* wgt  = (const float*)d_in[5];

    build_tables<<<N_/8, 256>>>(mux, muy, sx, sy);          // 1024 warps, warp-per-neuron
    main_kernel<<<dim3(KS_, NT_), 256>>>(x, wgt);           // 296 CTAs = 2/SM
    reduce_kernel<<<(B_*N_)/256, 256>>>((float*)d_out);
}